// round 1
// baseline (speedup 1.0000x reference)
#include <cuda_runtime.h>
#include <math.h>

// Problem constants
#define D_DIM 2048
#define S_LEN 2048
#define B_SZ  4
#define NHEAD 16
#define HD    128
#define MROWS (B_SZ * S_LEN)   // 8192

// ---------------------------------------------------------------------------
// Scratch (device globals: allocation-guard-safe)
// ---------------------------------------------------------------------------
__device__ float g_Q[(size_t)MROWS * D_DIM];
__device__ float g_K[(size_t)MROWS * D_DIM];
__device__ float g_V[(size_t)MROWS * D_DIM];
__device__ float g_O[(size_t)MROWS * D_DIM];

// ---------------------------------------------------------------------------
// SGEMM: C[M,N] = A[M,K] * B[N,K]^T   (both A and B are K-contiguous)
// 128x128 block tile, BK=16, 256 threads, 8x8 micro tile per thread.
// ---------------------------------------------------------------------------
__global__ __launch_bounds__(256, 2)
void sgemm_nt_kernel(const float* __restrict__ A,
                     const float* __restrict__ B,
                     float* __restrict__ C,
                     int M, int N, int K)
{
    __shared__ float As[16][132];
    __shared__ float Bs[16][132];

    const int tid = threadIdx.x;
    const int tx  = tid & 15;
    const int ty  = tid >> 4;
    const int bm0 = blockIdx.y * 128;
    const int bn0 = blockIdx.x * 128;

    const float* Aptr = A + (size_t)bm0 * K;
    const float* Bptr = B + (size_t)bn0 * K;

    float acc[8][8];
    #pragma unroll
    for (int i = 0; i < 8; ++i)
        #pragma unroll
        for (int j = 0; j < 8; ++j) acc[i][j] = 0.0f;

    for (int k0 = 0; k0 < K; k0 += 16) {
        // Load A/B tiles transposed into smem (k-major): 512 float4 each.
        #pragma unroll
        for (int it = 0; it < 2; ++it) {
            int idx = tid + it * 256;        // 0..511
            int row = idx >> 2;              // 0..127
            int kq  = (idx & 3) << 2;        // 0,4,8,12
            float4 a = *(const float4*)(Aptr + (size_t)row * K + k0 + kq);
            As[kq + 0][row] = a.x; As[kq + 1][row] = a.y;
            As[kq + 2][row] = a.z; As[kq + 3][row] = a.w;
            float4 b = *(const float4*)(Bptr + (size_t)row * K + k0 + kq);
            Bs[kq + 0][row] = b.x; Bs[kq + 1][row] = b.y;
            Bs[kq + 2][row] = b.z; Bs[kq + 3][row] = b.w;
        }
        __syncthreads();

        #pragma unroll
        for (int k = 0; k < 16; ++k) {
            float a[8], b[8];
            #pragma unroll
            for (int i = 0; i < 4; ++i) a[i]     = As[k][ty * 8 + i];
            #pragma unroll
            for (int i = 0; i < 4; ++i) a[4 + i] = As[k][ty * 8 + 4 + i];
            #pragma unroll
            for (int j = 0; j < 4; ++j) b[j]     = Bs[k][tx * 8 + j];
            #pragma unroll
            for (int j = 0; j < 4; ++j) b[4 + j] = Bs[k][tx * 8 + 4 + j];
            #pragma unroll
            for (int i = 0; i < 8; ++i)
                #pragma unroll
                for (int j = 0; j < 8; ++j)
                    acc[i][j] = fmaf(a[i], b[j], acc[i][j]);
        }
        __syncthreads();
    }

    #pragma unroll
    for (int i = 0; i < 8; ++i) {
        float* crow = C + (size_t)(bm0 + ty * 8 + i) * N + bn0 + tx * 8;
        *(float4*)(crow)     = make_float4(acc[i][0], acc[i][1], acc[i][2], acc[i][3]);
        *(float4*)(crow + 4) = make_float4(acc[i][4], acc[i][5], acc[i][6], acc[i][7]);
    }
}

// ---------------------------------------------------------------------------
// Causal flash attention (fp32). One block per (q-tile of 64, head, batch).
// 256 threads (16x16). Scores micro-tile 4x4; O micro-tile 4x8 (cols cj*16+tx).
// Q/K tiles stored k-major in smem with ld=68 (16B aligned, conflict-free
// LDS.128 frag loads); V row-major ld=128; P staged in smem ld=68.
// ---------------------------------------------------------------------------
#define LDQK 68
#define LDV  128
#define LDP  68
#define ATT_SMEM_FLOATS (2 * 128 * LDQK + 64 * LDV + 64 * LDP)
#define ATT_SMEM_BYTES  (ATT_SMEM_FLOATS * 4)

__global__ __launch_bounds__(256, 1)
void attn_kernel(const float* __restrict__ Q,
                 const float* __restrict__ K,
                 const float* __restrict__ V,
                 float* __restrict__ O)
{
    extern __shared__ float sm[];
    float* Qs = sm;                       // [128][68] k-major
    float* Ks = Qs + 128 * LDQK;          // [128][68] k-major
    float* Vs = Ks + 128 * LDQK;          // [64][128] row-major
    float* Ps = Vs + 64 * LDV;            // [64][68]

    const int tid = threadIdx.x;
    const int tx  = tid & 15;
    const int ty  = tid >> 4;
    const int q0  = blockIdx.x * 64;
    const int h   = blockIdx.y;
    const int b   = blockIdx.z;

    const size_t base = ((size_t)b * S_LEN) * D_DIM + (size_t)h * HD;
    const float scale = 0.08838834764831845f;  // 1/sqrt(128)

    // Load Q tile transposed into smem: 64 rows x 128 cols -> 2048 float4.
    #pragma unroll
    for (int it = 0; it < 8; ++it) {
        int idx = tid + it * 256;          // 0..2047
        int row = idx >> 5;                // 0..63
        int kq  = (idx & 31) << 2;         // 0..124
        float4 v4 = *(const float4*)(Q + base + (size_t)(q0 + row) * D_DIM + kq);
        Qs[(kq + 0) * LDQK + row] = v4.x;
        Qs[(kq + 1) * LDQK + row] = v4.y;
        Qs[(kq + 2) * LDQK + row] = v4.z;
        Qs[(kq + 3) * LDQK + row] = v4.w;
    }

    float o[4][8];
    float mrow[4], lrow[4];
    #pragma unroll
    for (int i = 0; i < 4; ++i) {
        mrow[i] = -INFINITY; lrow[i] = 0.0f;
        #pragma unroll
        for (int cj = 0; cj < 8; ++cj) o[i][cj] = 0.0f;
    }

    const int ntiles = q0 / 64 + 1;
    for (int t = 0; t < ntiles; ++t) {
        const int k0 = t * 64;
        __syncthreads();   // prior-iter smem reads done; Q tile visible on t=0

        // Load K (transposed) and V (row-major) tiles.
        #pragma unroll
        for (int it = 0; it < 8; ++it) {
            int idx = tid + it * 256;
            int row = idx >> 5;
            int kq  = (idx & 31) << 2;
            float4 kv = *(const float4*)(K + base + (size_t)(k0 + row) * D_DIM + kq);
            Ks[(kq + 0) * LDQK + row] = kv.x;
            Ks[(kq + 1) * LDQK + row] = kv.y;
            Ks[(kq + 2) * LDQK + row] = kv.z;
            Ks[(kq + 3) * LDQK + row] = kv.w;
            float4 vv = *(const float4*)(V + base + (size_t)(k0 + row) * D_DIM + kq);
            *(float4*)(Vs + row * LDV + kq) = vv;
        }
        __syncthreads();

        // Scores: S[4][4] = Q[rows ty*4+i] . K[rows tx*4+j]
        float s[4][4];
        #pragma unroll
        for (int i = 0; i < 4; ++i)
            #pragma unroll
            for (int j = 0; j < 4; ++j) s[i][j] = 0.0f;

        #pragma unroll 4
        for (int k = 0; k < 128; ++k) {
            float a[4], bb[4];
            *(float4*)a  = *(const float4*)(Qs + k * LDQK + ty * 4);
            *(float4*)bb = *(const float4*)(Ks + k * LDQK + tx * 4);
            #pragma unroll
            for (int i = 0; i < 4; ++i)
                #pragma unroll
                for (int j = 0; j < 4; ++j)
                    s[i][j] = fmaf(a[i], bb[j], s[i][j]);
        }

        // Causal mask: only the diagonal tile needs it.
        if (k0 == q0) {
            #pragma unroll
            for (int i = 0; i < 4; ++i) {
                int qg = ty * 4 + i;
                #pragma unroll
                for (int j = 0; j < 4; ++j)
                    if (tx * 4 + j > qg) s[i][j] = -INFINITY;
            }
        }

        // Online softmax per row (row owned by the 16 threads sharing ty).
        #pragma unroll
        for (int i = 0; i < 4; ++i) {
            float r = -INFINITY;
            #pragma unroll
            for (int j = 0; j < 4; ++j) {
                s[i][j] *= scale;
                r = fmaxf(r, s[i][j]);
            }
            #pragma unroll
            for (int off = 8; off >= 1; off >>= 1)
                r = fmaxf(r, __shfl_xor_sync(0xffffffffu, r, off, 16));
            float mnew  = fmaxf(mrow[i], r);
            float alpha = __expf(mrow[i] - mnew);
            mrow[i] = mnew;
            float psum = 0.0f;
            #pragma unroll
            for (int j = 0; j < 4; ++j) {
                float p = __expf(s[i][j] - mnew);
                s[i][j] = p;
                psum += p;
            }
            #pragma unroll
            for (int off = 8; off >= 1; off >>= 1)
                psum += __shfl_xor_sync(0xffffffffu, psum, off, 16);
            lrow[i] = lrow[i] * alpha + psum;
            #pragma unroll
            for (int cj = 0; cj < 8; ++cj) o[i][cj] *= alpha;
        }

        // Stage P to smem, then O += P @ V.
        #pragma unroll
        for (int i = 0; i < 4; ++i)
            *(float4*)(Ps + (ty * 4 + i) * LDP + tx * 4) =
                make_float4(s[i][0], s[i][1], s[i][2], s[i][3]);
        __syncthreads();

        #pragma unroll 4
        for (int n = 0; n < 64; ++n) {
            float pa[4];
            #pragma unroll
            for (int i = 0; i < 4; ++i) pa[i] = Ps[(ty * 4 + i) * LDP + n];
            float pv[8];
            #pragma unroll
            for (int cj = 0; cj < 8; ++cj) pv[cj] = Vs[n * LDV + cj * 16 + tx];
            #pragma unroll
            for (int i = 0; i < 4; ++i)
                #pragma unroll
                for (int cj = 0; cj < 8; ++cj)
                    o[i][cj] = fmaf(pa[i], pv[cj], o[i][cj]);
        }
    }

    // Epilogue: normalize and write O in [b, s, h*128+hd] layout.
    #pragma unroll
    for (int i = 0; i < 4; ++i) {
        float inv = 1.0f / lrow[i];
        size_t orow = base + (size_t)(q0 + ty * 4 + i) * D_DIM;
        #pragma unroll
        for (int cj = 0; cj < 8; ++cj)
            O[orow + cj * 16 + tx] = o[i][cj] * inv;
    }
}

// ---------------------------------------------------------------------------
// Launch
// ---------------------------------------------------------------------------
extern "C" void kernel_launch(void* const* d_in, const int* in_sizes, int n_in,
                              void* d_out, int out_size)
{
    const float* x  = (const float*)d_in[0];
    const float* wq = (const float*)d_in[1];
    const float* wk = (const float*)d_in[2];
    const float* wv = (const float*)d_in[3];
    const float* wo = (const float*)d_in[4];
    float* out = (float*)d_out;

    float *Qp, *Kp, *Vp, *Op;
    cudaGetSymbolAddress((void**)&Qp, g_Q);
    cudaGetSymbolAddress((void**)&Kp, g_K);
    cudaGetSymbolAddress((void**)&Vp, g_V);
    cudaGetSymbolAddress((void**)&Op, g_O);

    static bool attr_set = false;
    if (!attr_set) {
        cudaFuncSetAttribute(attn_kernel,
                             cudaFuncAttributeMaxDynamicSharedMemorySize,
                             ATT_SMEM_BYTES);
        attr_set = true;
    }

    dim3 gemm_grid(D_DIM / 128, MROWS / 128);   // (16, 64)
    dim3 gemm_block(256);

    // Q/K/V projections
    sgemm_nt_kernel<<<gemm_grid, gemm_block>>>(x, wq, Qp, MROWS, D_DIM, D_DIM);
    sgemm_nt_kernel<<<gemm_grid, gemm_block>>>(x, wk, Kp, MROWS, D_DIM, D_DIM);
    sgemm_nt_kernel<<<gemm_grid, gemm_block>>>(x, wv, Vp, MROWS, D_DIM, D_DIM);

    // Causal flash attention
    dim3 attn_grid(S_LEN / 64, NHEAD, B_SZ);    // (32, 16, 4)
    attn_kernel<<<attn_grid, 256, ATT_SMEM_BYTES>>>(Qp, Kp, Vp, Op);

    // Output projection
    sgemm_nt_kernel<<<gemm_grid, gemm_block>>>(Op, wo, out, MROWS, D_DIM, D_DIM);
}

// round 3
// speedup vs baseline: 1.9859x; 1.9859x over previous
#include <cuda_runtime.h>
#include <math.h>
#include <cstdint>

// Problem constants
#define D_DIM 2048
#define S_LEN 2048
#define B_SZ  4
#define NHEAD 16
#define HD    128
#define MROWS (B_SZ * S_LEN)   // 8192

// ---------------------------------------------------------------------------
// Scratch (device globals: allocation-guard-safe)
// ---------------------------------------------------------------------------
__device__ float g_Q[(size_t)MROWS * D_DIM];
__device__ float g_K[(size_t)MROWS * D_DIM];
__device__ float g_V[(size_t)MROWS * D_DIM];
__device__ float g_O[(size_t)MROWS * D_DIM];
__device__ float g_xt[(size_t)MROWS * D_DIM];          // tf32-rounded x
__device__ float g_wqt[(size_t)D_DIM * D_DIM];
__device__ float g_wkt[(size_t)D_DIM * D_DIM];
__device__ float g_wvt[(size_t)D_DIM * D_DIM];
__device__ float g_wot[(size_t)D_DIM * D_DIM];

// ---------------------------------------------------------------------------
// cp.async helpers
// ---------------------------------------------------------------------------
__device__ __forceinline__ uint32_t smem_u32(const void* p) {
    uint32_t a;
    asm("{ .reg .u64 t; cvta.to.shared.u64 t, %1; cvt.u32.u64 %0, t; }"
        : "=r"(a) : "l"(p));
    return a;
}
__device__ __forceinline__ void cp_async16(uint32_t saddr, const void* gaddr) {
    asm volatile("cp.async.cg.shared.global [%0], [%1], 16;"
                 :: "r"(saddr), "l"(gaddr) : "memory");
}
__device__ __forceinline__ void cp_commit() {
    asm volatile("cp.async.commit_group;" ::: "memory");
}
template <int N> __device__ __forceinline__ void cp_wait() {
    asm volatile("cp.async.wait_group %0;" :: "n"(N) : "memory");
}

// ---------------------------------------------------------------------------
// tf32 rounding pass (RNA): fp32 -> tf32-valued fp32 (HMMA truncation lossless)
// ---------------------------------------------------------------------------
__device__ __forceinline__ float to_tf32(float x) {
    float r;
    asm("cvt.rna.tf32.f32 %0, %1;" : "=f"(r) : "f"(x));
    return r;
}
__global__ void tf32_cvt_kernel(const float4* __restrict__ in,
                                float4* __restrict__ out, int n4) {
    int i = blockIdx.x * blockDim.x + threadIdx.x;
    if (i < n4) {
        float4 v = in[i];
        v.x = to_tf32(v.x); v.y = to_tf32(v.y);
        v.z = to_tf32(v.z); v.w = to_tf32(v.w);
        out[i] = v;
    }
}

// ---------------------------------------------------------------------------
// HMMA tf32 GEMM: C[M,N] = A[M,K] * B[N,K]^T (A, B K-contiguous, tf32-valued)
// 128x128 CTA tile, BK=32, 3-stage cp.async pipeline, XOR-swizzled smem,
// 8 warps (4m x 2n), warp tile 32x64 via m16n8k8 mma.sync.
// ---------------------------------------------------------------------------
#define BM 128
#define BN 128
#define BK 32
#define NSTAGE 3
#define ATILE_BYTES (BM * BK * 4)                        // 16384
#define STAGE_BYTES (2 * ATILE_BYTES)                    // 32768
#define GEMM_SMEM_BYTES (NSTAGE * STAGE_BYTES)           // 98304

// XOR-swizzled smem tile: row-major 128 rows x 32 floats (128B/row);
// 16B chunk c of row r lands at r*128 + ((c ^ (r&7))<<4).
__device__ __forceinline__ float lds_sw(const float* base, int row, int col) {
    int c = col >> 2, w = col & 3;
    return base[row * 32 + (((c ^ (row & 7)) << 2) | w)];
}

__device__ __forceinline__ void mma_tf32(float* d, const uint32_t* a, const uint32_t* b) {
    asm volatile(
        "mma.sync.aligned.m16n8k8.row.col.f32.tf32.tf32.f32 "
        "{%0,%1,%2,%3}, {%4,%5,%6,%7}, {%8,%9}, {%0,%1,%2,%3};"
        : "+f"(d[0]), "+f"(d[1]), "+f"(d[2]), "+f"(d[3])
        : "r"(a[0]), "r"(a[1]), "r"(a[2]), "r"(a[3]), "r"(b[0]), "r"(b[1]));
}

__device__ __forceinline__ void load_stage(uint32_t sbase,
                                           const float* __restrict__ A,
                                           const float* __restrict__ B,
                                           int K, int arow0, int brow0, int k0,
                                           int tid) {
    #pragma unroll
    for (int i = 0; i < 4; ++i) {
        int idx = tid + i * 256;           // 0..1023
        int r = idx >> 3;                  // row 0..127
        int c = idx & 7;                   // 16B chunk 0..7
        uint32_t soff = (uint32_t)(r * 128 + ((c ^ (r & 7)) << 4));
        cp_async16(sbase + soff, A + (size_t)(arow0 + r) * K + k0 + c * 4);
    }
    #pragma unroll
    for (int i = 0; i < 4; ++i) {
        int idx = tid + i * 256;
        int r = idx >> 3;
        int c = idx & 7;
        uint32_t soff = (uint32_t)(r * 128 + ((c ^ (r & 7)) << 4));
        cp_async16(sbase + ATILE_BYTES + soff, B + (size_t)(brow0 + r) * K + k0 + c * 4);
    }
    cp_commit();
}

__global__ __launch_bounds__(256, 2)
void gemm_tf32_kernel(const float* __restrict__ A,
                      const float* __restrict__ B,
                      float* __restrict__ C,
                      int M, int N, int K)
{
    extern __shared__ char smem[];
    const uint32_t sbase = smem_u32(smem);
    const int tid  = threadIdx.x;
    const int wid  = tid >> 5;
    const int lane = tid & 31;
    const int wm   = wid >> 1;             // 0..3 -> m offset wm*32
    const int wn   = wid & 1;              // 0..1 -> n offset wn*64
    const int g    = lane >> 2;            // group id 0..7
    const int t    = lane & 3;             // thread-in-group 0..3
    const int bm0 = blockIdx.y * BM;
    const int bn0 = blockIdx.x * BN;

    float acc[2][8][4];
    #pragma unroll
    for (int mt = 0; mt < 2; ++mt)
        #pragma unroll
        for (int nt = 0; nt < 8; ++nt)
            #pragma unroll
            for (int i = 0; i < 4; ++i) acc[mt][nt][i] = 0.0f;

    const int KT = K / BK;   // 64

    load_stage(sbase + 0 * STAGE_BYTES, A, B, K, bm0, bn0, 0 * BK, tid);
    load_stage(sbase + 1 * STAGE_BYTES, A, B, K, bm0, bn0, 1 * BK, tid);

    for (int kt = 0; kt < KT; ++kt) {
        const int s = kt % 3;
        if (kt == KT - 1) cp_wait<0>(); else cp_wait<1>();
        __syncthreads();

        // Prefetch stage kt+2 (slot was last read in iteration kt-1).
        if (kt + 2 < KT)
            load_stage(sbase + (uint32_t)((kt + 2) % 3) * STAGE_BYTES, A, B, K,
                       bm0, bn0, (kt + 2) * BK, tid);

        const float* Abase = (const float*)(smem + (size_t)s * STAGE_BYTES);
        const float* Bbase = Abase + ATILE_BYTES / 4;

        #pragma unroll
        for (int kk = 0; kk < 4; ++kk) {
            const int k = kk * 8;
            uint32_t a[2][4];
            #pragma unroll
            for (int mt = 0; mt < 2; ++mt) {
                int r0 = wm * 32 + mt * 16 + g;
                a[mt][0] = __float_as_uint(lds_sw(Abase, r0,     k + t));
                a[mt][1] = __float_as_uint(lds_sw(Abase, r0 + 8, k + t));
                a[mt][2] = __float_as_uint(lds_sw(Abase, r0,     k + 4 + t));
                a[mt][3] = __float_as_uint(lds_sw(Abase, r0 + 8, k + 4 + t));
            }
            uint32_t b[8][2];
            #pragma unroll
            for (int nt = 0; nt < 8; ++nt) {
                int rb = wn * 64 + nt * 8 + g;
                b[nt][0] = __float_as_uint(lds_sw(Bbase, rb, k + t));
                b[nt][1] = __float_as_uint(lds_sw(Bbase, rb, k + 4 + t));
            }
            #pragma unroll
            for (int mt = 0; mt < 2; ++mt)
                #pragma unroll
                for (int nt = 0; nt < 8; ++nt)
                    mma_tf32(acc[mt][nt], a[mt], b[nt]);
        }
    }

    // Epilogue: direct float2 stores (c0,c1) at (row, col), (c2,c3) at (row+8).
    #pragma unroll
    for (int mt = 0; mt < 2; ++mt) {
        int row = bm0 + wm * 32 + mt * 16 + g;
        #pragma unroll
        for (int nt = 0; nt < 8; ++nt) {
            int col = bn0 + wn * 64 + nt * 8 + t * 2;
            *(float2*)(C + (size_t)row * N + col) =
                make_float2(acc[mt][nt][0], acc[mt][nt][1]);
            *(float2*)(C + (size_t)(row + 8) * N + col) =
                make_float2(acc[mt][nt][2], acc[mt][nt][3]);
        }
    }
}

// ---------------------------------------------------------------------------
// Causal flash attention (fp32) — unchanged.
// ---------------------------------------------------------------------------
#define LDQK 68
#define LDV  128
#define LDP  68
#define ATT_SMEM_FLOATS (2 * 128 * LDQK + 64 * LDV + 64 * LDP)
#define ATT_SMEM_BYTES  (ATT_SMEM_FLOATS * 4)

__global__ __launch_bounds__(256, 1)
void attn_kernel(const float* __restrict__ Q,
                 const float* __restrict__ K,
                 const float* __restrict__ V,
                 float* __restrict__ O)
{
    extern __shared__ float sm[];
    float* Qs = sm;
    float* Ks = Qs + 128 * LDQK;
    float* Vs = Ks + 128 * LDQK;
    float* Ps = Vs + 64 * LDV;

    const int tid = threadIdx.x;
    const int tx  = tid & 15;
    const int ty  = tid >> 4;
    const int q0  = blockIdx.x * 64;
    const int h   = blockIdx.y;
    const int b   = blockIdx.z;

    const size_t base = ((size_t)b * S_LEN) * D_DIM + (size_t)h * HD;
    const float scale = 0.08838834764831845f;

    #pragma unroll
    for (int it = 0; it < 8; ++it) {
        int idx = tid + it * 256;
        int row = idx >> 5;
        int kq  = (idx & 31) << 2;
        float4 v4 = *(const float4*)(Q + base + (size_t)(q0 + row) * D_DIM + kq);
        Qs[(kq + 0) * LDQK + row] = v4.x;
        Qs[(kq + 1) * LDQK + row] = v4.y;
        Qs[(kq + 2) * LDQK + row] = v4.z;
        Qs[(kq + 3) * LDQK + row] = v4.w;
    }

    float o[4][8];
    float mrow[4], lrow[4];
    #pragma unroll
    for (int i = 0; i < 4; ++i) {
        mrow[i] = -INFINITY; lrow[i] = 0.0f;
        #pragma unroll
        for (int cj = 0; cj < 8; ++cj) o[i][cj] = 0.0f;
    }

    const int ntiles = q0 / 64 + 1;
    for (int t = 0; t < ntiles; ++t) {
        const int k0 = t * 64;
        __syncthreads();

        #pragma unroll
        for (int it = 0; it < 8; ++it) {
            int idx = tid + it * 256;
            int row = idx >> 5;
            int kq  = (idx & 31) << 2;
            float4 kv = *(const float4*)(K + base + (size_t)(k0 + row) * D_DIM + kq);
            Ks[(kq + 0) * LDQK + row] = kv.x;
            Ks[(kq + 1) * LDQK + row] = kv.y;
            Ks[(kq + 2) * LDQK + row] = kv.z;
            Ks[(kq + 3) * LDQK + row] = kv.w;
            float4 vv = *(const float4*)(V + base + (size_t)(k0 + row) * D_DIM + kq);
            *(float4*)(Vs + row * LDV + kq) = vv;
        }
        __syncthreads();

        float s[4][4];
        #pragma unroll
        for (int i = 0; i < 4; ++i)
            #pragma unroll
            for (int j = 0; j < 4; ++j) s[i][j] = 0.0f;

        #pragma unroll 4
        for (int k = 0; k < 128; ++k) {
            float a[4], bb[4];
            *(float4*)a  = *(const float4*)(Qs + k * LDQK + ty * 4);
            *(float4*)bb = *(const float4*)(Ks + k * LDQK + tx * 4);
            #pragma unroll
            for (int i = 0; i < 4; ++i)
                #pragma unroll
                for (int j = 0; j < 4; ++j)
                    s[i][j] = fmaf(a[i], bb[j], s[i][j]);
        }

        if (k0 == q0) {
            #pragma unroll
            for (int i = 0; i < 4; ++i) {
                int qg = ty * 4 + i;
                #pragma unroll
                for (int j = 0; j < 4; ++j)
                    if (tx * 4 + j > qg) s[i][j] = -INFINITY;
            }
        }

        #pragma unroll
        for (int i = 0; i < 4; ++i) {
            float r = -INFINITY;
            #pragma unroll
            for (int j = 0; j < 4; ++j) {
                s[i][j] *= scale;
                r = fmaxf(r, s[i][j]);
            }
            #pragma unroll
            for (int off = 8; off >= 1; off >>= 1)
                r = fmaxf(r, __shfl_xor_sync(0xffffffffu, r, off, 16));
            float mnew  = fmaxf(mrow[i], r);
            float alpha = __expf(mrow[i] - mnew);
            mrow[i] = mnew;
            float psum = 0.0f;
            #pragma unroll
            for (int j = 0; j < 4; ++j) {
                float p = __expf(s[i][j] - mnew);
                s[i][j] = p;
                psum += p;
            }
            #pragma unroll
            for (int off = 8; off >= 1; off >>= 1)
                psum += __shfl_xor_sync(0xffffffffu, psum, off, 16);
            lrow[i] = lrow[i] * alpha + psum;
            #pragma unroll
            for (int cj = 0; cj < 8; ++cj) o[i][cj] *= alpha;
        }

        #pragma unroll
        for (int i = 0; i < 4; ++i)
            *(float4*)(Ps + (ty * 4 + i) * LDP + tx * 4) =
                make_float4(s[i][0], s[i][1], s[i][2], s[i][3]);
        __syncthreads();

        #pragma unroll 4
        for (int n = 0; n < 64; ++n) {
            float pa[4];
            #pragma unroll
            for (int i = 0; i < 4; ++i) pa[i] = Ps[(ty * 4 + i) * LDP + n];
            float pv[8];
            #pragma unroll
            for (int cj = 0; cj < 8; ++cj) pv[cj] = Vs[n * LDV + cj * 16 + tx];
            #pragma unroll
            for (int i = 0; i < 4; ++i)
                #pragma unroll
                for (int cj = 0; cj < 8; ++cj)
                    o[i][cj] = fmaf(pa[i], pv[cj], o[i][cj]);
        }
    }

    #pragma unroll
    for (int i = 0; i < 4; ++i) {
        float inv = 1.0f / lrow[i];
        size_t orow = base + (size_t)(q0 + ty * 4 + i) * D_DIM;
        #pragma unroll
        for (int cj = 0; cj < 8; ++cj)
            O[orow + cj * 16 + tx] = o[i][cj] * inv;
    }
}

// ---------------------------------------------------------------------------
// Launch
// ---------------------------------------------------------------------------
extern "C" void kernel_launch(void* const* d_in, const int* in_sizes, int n_in,
                              void* d_out, int out_size)
{
    const float* x  = (const float*)d_in[0];
    const float* wq = (const float*)d_in[1];
    const float* wk = (const float*)d_in[2];
    const float* wv = (const float*)d_in[3];
    const float* wo = (const float*)d_in[4];
    float* out = (float*)d_out;

    float *Qp, *Kp, *Vp, *Op, *xt, *wqt, *wkt, *wvt, *wot;
    cudaGetSymbolAddress((void**)&Qp,  g_Q);
    cudaGetSymbolAddress((void**)&Kp,  g_K);
    cudaGetSymbolAddress((void**)&Vp,  g_V);
    cudaGetSymbolAddress((void**)&Op,  g_O);
    cudaGetSymbolAddress((void**)&xt,  g_xt);
    cudaGetSymbolAddress((void**)&wqt, g_wqt);
    cudaGetSymbolAddress((void**)&wkt, g_wkt);
    cudaGetSymbolAddress((void**)&wvt, g_wvt);
    cudaGetSymbolAddress((void**)&wot, g_wot);

    static bool attr_set = false;
    if (!attr_set) {
        cudaFuncSetAttribute(attn_kernel,
                             cudaFuncAttributeMaxDynamicSharedMemorySize,
                             ATT_SMEM_BYTES);
        cudaFuncSetAttribute(gemm_tf32_kernel,
                             cudaFuncAttributeMaxDynamicSharedMemorySize,
                             GEMM_SMEM_BYTES);
        attr_set = true;
    }

    const int n4x = MROWS * D_DIM / 4;       // 4194304
    const int n4w = D_DIM * D_DIM / 4;       // 1048576

    // tf32-round all GEMM inputs (RNA)
    tf32_cvt_kernel<<<n4x / 256, 256>>>((const float4*)x,  (float4*)xt,  n4x);
    tf32_cvt_kernel<<<n4w / 256, 256>>>((const float4*)wq, (float4*)wqt, n4w);
    tf32_cvt_kernel<<<n4w / 256, 256>>>((const float4*)wk, (float4*)wkt, n4w);
    tf32_cvt_kernel<<<n4w / 256, 256>>>((const float4*)wv, (float4*)wvt, n4w);
    tf32_cvt_kernel<<<n4w / 256, 256>>>((const float4*)wo, (float4*)wot, n4w);

    dim3 gemm_grid(D_DIM / BN, MROWS / BM);   // (16, 64)

    gemm_tf32_kernel<<<gemm_grid, 256, GEMM_SMEM_BYTES>>>(xt, wqt, Qp, MROWS, D_DIM, D_DIM);
    gemm_tf32_kernel<<<gemm_grid, 256, GEMM_SMEM_BYTES>>>(xt, wkt, Kp, MROWS, D_DIM, D_DIM);
    gemm_tf32_kernel<<<gemm_grid, 256, GEMM_SMEM_BYTES>>>(xt, wvt, Vp, MROWS, D_DIM, D_DIM);

    dim3 attn_grid(S_LEN / 64, NHEAD, B_SZ);
    attn_kernel<<<attn_grid, 256, ATT_SMEM_BYTES>>>(Qp, Kp, Vp, Op);

    // tf32-round attention output in place, then output projection
    tf32_cvt_kernel<<<n4x / 256, 256>>>((const float4*)Op, (float4*)Op, n4x);
    gemm_tf32_kernel<<<gemm_grid, 256, GEMM_SMEM_BYTES>>>(Op, wot, out, MROWS, D_DIM, D_DIM);
}

// round 4
// speedup vs baseline: 3.8095x; 1.9182x over previous
#include <cuda_runtime.h>
#include <math.h>
#include <cstdint>

// Problem constants
#define D_DIM 2048
#define S_LEN 2048
#define B_SZ  4
#define NHEAD 16
#define HD    128
#define MROWS (B_SZ * S_LEN)   // 8192

// ---------------------------------------------------------------------------
// Scratch (device globals: allocation-guard-safe)
// ---------------------------------------------------------------------------
__device__ float g_Q[(size_t)MROWS * D_DIM];
__device__ float g_K[(size_t)MROWS * D_DIM];
__device__ float g_V[(size_t)MROWS * D_DIM];
__device__ float g_O[(size_t)MROWS * D_DIM];
__device__ float g_xt[(size_t)MROWS * D_DIM];          // tf32-rounded x
__device__ float g_wqt[(size_t)D_DIM * D_DIM];
__device__ float g_wkt[(size_t)D_DIM * D_DIM];
__device__ float g_wvt[(size_t)D_DIM * D_DIM];
__device__ float g_wot[(size_t)D_DIM * D_DIM];

// ---------------------------------------------------------------------------
// Helpers
// ---------------------------------------------------------------------------
__device__ __forceinline__ uint32_t smem_u32(const void* p) {
    uint32_t a;
    asm("{ .reg .u64 t; cvta.to.shared.u64 t, %1; cvt.u32.u64 %0, t; }"
        : "=r"(a) : "l"(p));
    return a;
}
__device__ __forceinline__ void cp_async16(uint32_t saddr, const void* gaddr) {
    asm volatile("cp.async.cg.shared.global [%0], [%1], 16;"
                 :: "r"(saddr), "l"(gaddr) : "memory");
}
__device__ __forceinline__ void cp_commit() {
    asm volatile("cp.async.commit_group;" ::: "memory");
}
template <int N> __device__ __forceinline__ void cp_wait() {
    asm volatile("cp.async.wait_group %0;" :: "n"(N) : "memory");
}
__device__ __forceinline__ float to_tf32(float x) {
    float r;
    asm("cvt.rna.tf32.f32 %0, %1;" : "=f"(r) : "f"(x));
    return r;
}
__device__ __forceinline__ void mma_tf32(float* d, const uint32_t* a, const uint32_t* b) {
    asm volatile(
        "mma.sync.aligned.m16n8k8.row.col.f32.tf32.tf32.f32 "
        "{%0,%1,%2,%3}, {%4,%5,%6,%7}, {%8,%9}, {%0,%1,%2,%3};"
        : "+f"(d[0]), "+f"(d[1]), "+f"(d[2]), "+f"(d[3])
        : "r"(a[0]), "r"(a[1]), "r"(a[2]), "r"(a[3]), "r"(b[0]), "r"(b[1]));
}

__global__ void tf32_cvt_kernel(const float4* __restrict__ in,
                                float4* __restrict__ out, int n4) {
    int i = blockIdx.x * blockDim.x + threadIdx.x;
    if (i < n4) {
        float4 v = in[i];
        v.x = to_tf32(v.x); v.y = to_tf32(v.y);
        v.z = to_tf32(v.z); v.w = to_tf32(v.w);
        out[i] = v;
    }
}

// ---------------------------------------------------------------------------
// HMMA tf32 GEMM: C = A[M,K] * B[N,K]^T, optional tf32-rounding of C.
// ---------------------------------------------------------------------------
#define BM 128
#define BN 128
#define BK 32
#define ATILE_BYTES (BM * BK * 4)
#define STAGE_BYTES (2 * ATILE_BYTES)
#define GEMM_SMEM_BYTES (3 * STAGE_BYTES)

__device__ __forceinline__ float lds_sw32(const float* base, int row, int col) {
    int c = col >> 2, w = col & 3;
    return base[row * 32 + (((c ^ (row & 7)) << 2) | w)];
}

__device__ __forceinline__ void load_stage(uint32_t sbase,
                                           const float* __restrict__ A,
                                           const float* __restrict__ B,
                                           int K, int arow0, int brow0, int k0,
                                           int tid) {
    #pragma unroll
    for (int i = 0; i < 4; ++i) {
        int idx = tid + i * 256;
        int r = idx >> 3;
        int c = idx & 7;
        uint32_t soff = (uint32_t)(r * 128 + ((c ^ (r & 7)) << 4));
        cp_async16(sbase + soff, A + (size_t)(arow0 + r) * K + k0 + c * 4);
    }
    #pragma unroll
    for (int i = 0; i < 4; ++i) {
        int idx = tid + i * 256;
        int r = idx >> 3;
        int c = idx & 7;
        uint32_t soff = (uint32_t)(r * 128 + ((c ^ (r & 7)) << 4));
        cp_async16(sbase + ATILE_BYTES + soff, B + (size_t)(brow0 + r) * K + k0 + c * 4);
    }
    cp_commit();
}

template <bool ROUND>
__global__ __launch_bounds__(256, 2)
void gemm_tf32_kernel(const float* __restrict__ A,
                      const float* __restrict__ B,
                      float* __restrict__ C,
                      int M, int N, int K)
{
    extern __shared__ char smem[];
    const uint32_t sbase = smem_u32(smem);
    const int tid  = threadIdx.x;
    const int wid  = tid >> 5;
    const int lane = tid & 31;
    const int wm   = wid >> 1;
    const int wn   = wid & 1;
    const int g    = lane >> 2;
    const int t    = lane & 3;
    const int bm0 = blockIdx.y * BM;
    const int bn0 = blockIdx.x * BN;

    float acc[2][8][4];
    #pragma unroll
    for (int mt = 0; mt < 2; ++mt)
        #pragma unroll
        for (int nt = 0; nt < 8; ++nt)
            #pragma unroll
            for (int i = 0; i < 4; ++i) acc[mt][nt][i] = 0.0f;

    const int KT = K / BK;

    load_stage(sbase + 0 * STAGE_BYTES, A, B, K, bm0, bn0, 0 * BK, tid);
    load_stage(sbase + 1 * STAGE_BYTES, A, B, K, bm0, bn0, 1 * BK, tid);

    for (int kt = 0; kt < KT; ++kt) {
        const int s = kt % 3;
        if (kt == KT - 1) cp_wait<0>(); else cp_wait<1>();
        __syncthreads();

        if (kt + 2 < KT)
            load_stage(sbase + (uint32_t)((kt + 2) % 3) * STAGE_BYTES, A, B, K,
                       bm0, bn0, (kt + 2) * BK, tid);

        const float* Abase = (const float*)(smem + (size_t)s * STAGE_BYTES);
        const float* Bbase = Abase + ATILE_BYTES / 4;

        #pragma unroll
        for (int kk = 0; kk < 4; ++kk) {
            const int k = kk * 8;
            uint32_t a[2][4];
            #pragma unroll
            for (int mt = 0; mt < 2; ++mt) {
                int r0 = wm * 32 + mt * 16 + g;
                a[mt][0] = __float_as_uint(lds_sw32(Abase, r0,     k + t));
                a[mt][1] = __float_as_uint(lds_sw32(Abase, r0 + 8, k + t));
                a[mt][2] = __float_as_uint(lds_sw32(Abase, r0,     k + 4 + t));
                a[mt][3] = __float_as_uint(lds_sw32(Abase, r0 + 8, k + 4 + t));
            }
            uint32_t b[8][2];
            #pragma unroll
            for (int nt = 0; nt < 8; ++nt) {
                int rb = wn * 64 + nt * 8 + g;
                b[nt][0] = __float_as_uint(lds_sw32(Bbase, rb, k + t));
                b[nt][1] = __float_as_uint(lds_sw32(Bbase, rb, k + 4 + t));
            }
            #pragma unroll
            for (int mt = 0; mt < 2; ++mt)
                #pragma unroll
                for (int nt = 0; nt < 8; ++nt)
                    mma_tf32(acc[mt][nt], a[mt], b[nt]);
        }
    }

    #pragma unroll
    for (int mt = 0; mt < 2; ++mt) {
        int row = bm0 + wm * 32 + mt * 16 + g;
        #pragma unroll
        for (int nt = 0; nt < 8; ++nt) {
            int col = bn0 + wn * 64 + nt * 8 + t * 2;
            float c0 = acc[mt][nt][0], c1 = acc[mt][nt][1];
            float c2 = acc[mt][nt][2], c3 = acc[mt][nt][3];
            if (ROUND) { c0 = to_tf32(c0); c1 = to_tf32(c1);
                         c2 = to_tf32(c2); c3 = to_tf32(c3); }
            *(float2*)(C + (size_t)row * N + col)       = make_float2(c0, c1);
            *(float2*)(C + (size_t)(row + 8) * N + col) = make_float2(c2, c3);
        }
    }
}

// ---------------------------------------------------------------------------
// Tensor-core causal flash attention (tf32 mma, fp32 accumulate).
// Q-tile 128, KV-tile 64, 8 warps (16 q-rows each), 256 threads.
// Qs/Ks: XOR-swizzled (ld 128 floats); Vs: padded ld 132. KV double-buffered.
// ---------------------------------------------------------------------------
#define QT  128
#define KVT 64
#define LDV2 132
#define ATT_Q_OFF 0
#define ATT_K_OFF (128 * 128)                         // 16384
#define ATT_V_OFF (ATT_K_OFF + 2 * KVT * 128)         // 16384 + 16384
#define ATT_SMEM_FLOATS (ATT_V_OFF + 2 * KVT * LDV2)  // + 16896
#define ATT_SMEM_BYTES (ATT_SMEM_FLOATS * 4)          // 198656

__device__ __forceinline__ float lds_sw128(const float* base, int row, int col) {
    int c = col >> 2, w = col & 3;
    return base[row * 128 + (((c ^ (row & 7)) << 2) | w)];
}

__device__ __forceinline__ void attn_load_kv(uint32_t sbase, int stage,
                                             const float* __restrict__ K,
                                             const float* __restrict__ V,
                                             size_t gbase, int k0, int tid) {
    #pragma unroll
    for (int i = 0; i < 8; ++i) {
        int idx = tid + i * 256;           // 0..2047
        int r = idx >> 5;                  // 0..63
        int c = idx & 31;                  // 16B chunk
        uint32_t dst = sbase + 4u * (ATT_K_OFF + stage * KVT * 128 + r * 128)
                     + (uint32_t)((c ^ (r & 7)) << 4);
        cp_async16(dst, K + gbase + (size_t)(k0 + r) * D_DIM + c * 4);
    }
    #pragma unroll
    for (int i = 0; i < 8; ++i) {
        int idx = tid + i * 256;
        int r = idx >> 5;
        int c = idx & 31;
        uint32_t dst = sbase + 4u * (ATT_V_OFF + stage * KVT * LDV2 + r * LDV2)
                     + (uint32_t)(c << 4);
        cp_async16(dst, V + gbase + (size_t)(k0 + r) * D_DIM + c * 4);
    }
    cp_commit();
}

__global__ __launch_bounds__(256, 1)
void attn_mma_kernel(const float* __restrict__ Q,
                     const float* __restrict__ K,
                     const float* __restrict__ V,
                     float* __restrict__ O)
{
    extern __shared__ float sm[];
    const uint32_t sbase = smem_u32(sm);
    float* Qs = sm + ATT_Q_OFF;

    const int tid  = threadIdx.x;
    const int wid  = tid >> 5;
    const int lane = tid & 31;
    const int g    = lane >> 2;
    const int t    = lane & 3;
    const int q0 = blockIdx.x * QT;
    const int h  = blockIdx.y;
    const int b  = blockIdx.z;
    const size_t gbase = ((size_t)b * S_LEN) * D_DIM + (size_t)h * HD;
    const float scale = 0.08838834764831845f;  // 1/sqrt(128)

    // Q tile loads (swizzled), plus KV tile 0 into stage 0.
    #pragma unroll
    for (int i = 0; i < 16; ++i) {
        int idx = tid + i * 256;           // 0..4095
        int r = idx >> 5;                  // 0..127
        int c = idx & 31;
        uint32_t dst = sbase + 4u * (ATT_Q_OFF + r * 128)
                     + (uint32_t)((c ^ (r & 7)) << 4);
        cp_async16(dst, Q + gbase + (size_t)(q0 + r) * D_DIM + c * 4);
    }
    attn_load_kv(sbase, 0, K, V, gbase, 0, tid);

    float o[16][4];
    #pragma unroll
    for (int j = 0; j < 16; ++j)
        #pragma unroll
        for (int i = 0; i < 4; ++i) o[j][i] = 0.0f;
    float m2[2] = {-INFINITY, -INFINITY};
    float l2[2] = {0.0f, 0.0f};

    const int r0 = wid * 16;               // warp's row block within q-tile
    const int ntiles = q0 / KVT + 2;

    for (int tt = 0; tt < ntiles; ++tt) {
        const int s = tt & 1;
        cp_wait<0>();
        __syncthreads();
        if (tt + 1 < ntiles)
            attn_load_kv(sbase, s ^ 1, K, V, gbase, (tt + 1) * KVT, tid);

        const int kk0 = tt * KVT;
        // Warp fully masked on this tile? (all cols > all rows)
        if (kk0 <= q0 + r0 + 15) {
            const float* Ksb = sm + ATT_K_OFF + s * KVT * 128;
            const float* Vsb = sm + ATT_V_OFF + s * KVT * LDV2;

            // ---- QK^T: scores 16x64 per warp ----
            float sc[8][4];
            #pragma unroll
            for (int j = 0; j < 8; ++j)
                #pragma unroll
                for (int i = 0; i < 4; ++i) sc[j][i] = 0.0f;

            #pragma unroll
            for (int ks = 0; ks < 16; ++ks) {
                const int k = ks * 8;
                uint32_t a[4];
                a[0] = __float_as_uint(lds_sw128(Qs, r0 + g,     k + t));
                a[1] = __float_as_uint(lds_sw128(Qs, r0 + g + 8, k + t));
                a[2] = __float_as_uint(lds_sw128(Qs, r0 + g,     k + 4 + t));
                a[3] = __float_as_uint(lds_sw128(Qs, r0 + g + 8, k + 4 + t));
                #pragma unroll
                for (int j = 0; j < 8; ++j) {
                    uint32_t bb[2];
                    bb[0] = __float_as_uint(lds_sw128(Ksb, j * 8 + g, k + t));
                    bb[1] = __float_as_uint(lds_sw128(Ksb, j * 8 + g, k + 4 + t));
                    mma_tf32(sc[j], a, bb);
                }
            }

            // ---- causal mask (only near diagonal) ----
            if (kk0 + KVT - 1 > q0 + r0) {
                #pragma unroll
                for (int j = 0; j < 8; ++j) {
                    int colb = kk0 + j * 8 + 2 * t;
                    int rowa = q0 + r0 + g;
                    if (colb     > rowa)     sc[j][0] = -INFINITY;
                    if (colb + 1 > rowa)     sc[j][1] = -INFINITY;
                    if (colb     > rowa + 8) sc[j][2] = -INFINITY;
                    if (colb + 1 > rowa + 8) sc[j][3] = -INFINITY;
                }
            }

            // ---- online softmax (rows g and g+8) ----
            float alpha2[2];
            #pragma unroll
            for (int half = 0; half < 2; ++half) {
                const int i0 = half * 2;
                float rmax = -INFINITY;
                #pragma unroll
                for (int j = 0; j < 8; ++j)
                    rmax = fmaxf(rmax, fmaxf(sc[j][i0], sc[j][i0 + 1]));
                rmax = fmaxf(rmax, __shfl_xor_sync(0xffffffffu, rmax, 1));
                rmax = fmaxf(rmax, __shfl_xor_sync(0xffffffffu, rmax, 2));
                float mold = m2[half];
                float mnew = fmaxf(mold, rmax);
                float alpha = __expf((mold - mnew) * scale);
                float rsum = 0.0f;
                #pragma unroll
                for (int j = 0; j < 8; ++j) {
                    float p0 = to_tf32(__expf((sc[j][i0]     - mnew) * scale));
                    float p1 = to_tf32(__expf((sc[j][i0 + 1] - mnew) * scale));
                    sc[j][i0] = p0; sc[j][i0 + 1] = p1;
                    rsum += p0 + p1;
                }
                rsum += __shfl_xor_sync(0xffffffffu, rsum, 1);
                rsum += __shfl_xor_sync(0xffffffffu, rsum, 2);
                l2[half] = l2[half] * alpha + rsum;
                m2[half] = mnew;
                alpha2[half] = alpha;
            }
            #pragma unroll
            for (int j = 0; j < 16; ++j) {
                o[j][0] *= alpha2[0]; o[j][1] *= alpha2[0];
                o[j][2] *= alpha2[1]; o[j][3] *= alpha2[1];
            }

            // ---- PV: O += P @ V ----
            const int src0 = (lane & ~3) | (t >> 1);
            #pragma unroll
            for (int kk = 0; kk < 8; ++kk) {
                float c0 = sc[kk][0], c1 = sc[kk][1];
                float c2 = sc[kk][2], c3 = sc[kk][3];
                float u00 = __shfl_sync(0xffffffffu, c0, src0);
                float u01 = __shfl_sync(0xffffffffu, c1, src0);
                float u10 = __shfl_sync(0xffffffffu, c0, src0 + 2);
                float u11 = __shfl_sync(0xffffffffu, c1, src0 + 2);
                float u20 = __shfl_sync(0xffffffffu, c2, src0);
                float u21 = __shfl_sync(0xffffffffu, c3, src0);
                float u30 = __shfl_sync(0xffffffffu, c2, src0 + 2);
                float u31 = __shfl_sync(0xffffffffu, c3, src0 + 2);
                uint32_t a[4];
                a[0] = __float_as_uint((t & 1) ? u01 : u00);
                a[1] = __float_as_uint((t & 1) ? u21 : u20);
                a[2] = __float_as_uint((t & 1) ? u11 : u10);
                a[3] = __float_as_uint((t & 1) ? u31 : u30);
                const float* vr0 = Vsb + (kk * 8 + t) * LDV2;
                const float* vr1 = Vsb + (kk * 8 + t + 4) * LDV2;
                #pragma unroll
                for (int j = 0; j < 16; ++j) {
                    uint32_t bb[2];
                    bb[0] = __float_as_uint(vr0[j * 8 + g]);
                    bb[1] = __float_as_uint(vr1[j * 8 + g]);
                    mma_tf32(o[j], a, bb);
                }
            }
        }
    }

    // ---- epilogue: normalize, tf32-round, store ----
    const float inv0 = 1.0f / l2[0];
    const float inv1 = 1.0f / l2[1];
    const int rowa = q0 + r0 + g;
    #pragma unroll
    for (int j = 0; j < 16; ++j) {
        int col = j * 8 + 2 * t;
        *(float2*)(O + gbase + (size_t)rowa * D_DIM + col) =
            make_float2(to_tf32(o[j][0] * inv0), to_tf32(o[j][1] * inv0));
        *(float2*)(O + gbase + (size_t)(rowa + 8) * D_DIM + col) =
            make_float2(to_tf32(o[j][2] * inv1), to_tf32(o[j][3] * inv1));
    }
}

// ---------------------------------------------------------------------------
// Launch
// ---------------------------------------------------------------------------
extern "C" void kernel_launch(void* const* d_in, const int* in_sizes, int n_in,
                              void* d_out, int out_size)
{
    const float* x  = (const float*)d_in[0];
    const float* wq = (const float*)d_in[1];
    const float* wk = (const float*)d_in[2];
    const float* wv = (const float*)d_in[3];
    const float* wo = (const float*)d_in[4];
    float* out = (float*)d_out;

    float *Qp, *Kp, *Vp, *Op, *xt, *wqt, *wkt, *wvt, *wot;
    cudaGetSymbolAddress((void**)&Qp,  g_Q);
    cudaGetSymbolAddress((void**)&Kp,  g_K);
    cudaGetSymbolAddress((void**)&Vp,  g_V);
    cudaGetSymbolAddress((void**)&Op,  g_O);
    cudaGetSymbolAddress((void**)&xt,  g_xt);
    cudaGetSymbolAddress((void**)&wqt, g_wqt);
    cudaGetSymbolAddress((void**)&wkt, g_wkt);
    cudaGetSymbolAddress((void**)&wvt, g_wvt);
    cudaGetSymbolAddress((void**)&wot, g_wot);

    static bool attr_set = false;
    if (!attr_set) {
        cudaFuncSetAttribute(attn_mma_kernel,
                             cudaFuncAttributeMaxDynamicSharedMemorySize,
                             ATT_SMEM_BYTES);
        cudaFuncSetAttribute(gemm_tf32_kernel<true>,
                             cudaFuncAttributeMaxDynamicSharedMemorySize,
                             GEMM_SMEM_BYTES);
        cudaFuncSetAttribute(gemm_tf32_kernel<false>,
                             cudaFuncAttributeMaxDynamicSharedMemorySize,
                             GEMM_SMEM_BYTES);
        attr_set = true;
    }

    const int n4x = MROWS * D_DIM / 4;
    const int n4w = D_DIM * D_DIM / 4;

    // tf32-round GEMM inputs (RNA)
    tf32_cvt_kernel<<<n4x / 256, 256>>>((const float4*)x,  (float4*)xt,  n4x);
    tf32_cvt_kernel<<<n4w / 256, 256>>>((const float4*)wq, (float4*)wqt, n4w);
    tf32_cvt_kernel<<<n4w / 256, 256>>>((const float4*)wk, (float4*)wkt, n4w);
    tf32_cvt_kernel<<<n4w / 256, 256>>>((const float4*)wv, (float4*)wvt, n4w);
    tf32_cvt_kernel<<<n4w / 256, 256>>>((const float4*)wo, (float4*)wot, n4w);

    dim3 gemm_grid(D_DIM / BN, MROWS / BM);   // (16, 64)

    // Q/K/V projections — outputs tf32-rounded in epilogue.
    gemm_tf32_kernel<true><<<gemm_grid, 256, GEMM_SMEM_BYTES>>>(xt, wqt, Qp, MROWS, D_DIM, D_DIM);
    gemm_tf32_kernel<true><<<gemm_grid, 256, GEMM_SMEM_BYTES>>>(xt, wkt, Kp, MROWS, D_DIM, D_DIM);
    gemm_tf32_kernel<true><<<gemm_grid, 256, GEMM_SMEM_BYTES>>>(xt, wvt, Vp, MROWS, D_DIM, D_DIM);

    // Tensor-core causal flash attention (O tf32-rounded in epilogue).
    dim3 attn_grid(S_LEN / QT, NHEAD, B_SZ);  // (16, 16, 4)
    attn_mma_kernel<<<attn_grid, 256, ATT_SMEM_BYTES>>>(Qp, Kp, Vp, Op);

    // Output projection — exact fp32 store.
    gemm_tf32_kernel<false><<<gemm_grid, 256, GEMM_SMEM_BYTES>>>(Op, wot, out, MROWS, D_DIM, D_DIM);
}

// round 5
// speedup vs baseline: 7.5746x; 1.9884x over previous
#include <cuda_runtime.h>
#include <cuda_fp16.h>
#include <math.h>
#include <cstdint>

// Problem constants
#define D_DIM 2048
#define S_LEN 2048
#define B_SZ  4
#define NHEAD 16
#define HD    128
#define MROWS (B_SZ * S_LEN)   // 8192
#define NQKV  (3 * D_DIM)      // 6144

// ---------------------------------------------------------------------------
// Scratch (device globals: allocation-guard-safe)
// ---------------------------------------------------------------------------
__device__ __half g_xh[(size_t)MROWS * D_DIM];
__device__ __half g_wqkvh[(size_t)NQKV * D_DIM];     // [wq; wk; wv] rows
__device__ __half g_woh[(size_t)D_DIM * D_DIM];
__device__ __half g_QKVh[(size_t)MROWS * NQKV];      // Q|K|V per row
__device__ __half g_Oh[(size_t)MROWS * D_DIM];

// ---------------------------------------------------------------------------
// Helpers
// ---------------------------------------------------------------------------
__device__ __forceinline__ uint32_t smem_u32(const void* p) {
    uint32_t a;
    asm("{ .reg .u64 t; cvta.to.shared.u64 t, %1; cvt.u32.u64 %0, t; }"
        : "=r"(a) : "l"(p));
    return a;
}
__device__ __forceinline__ void cp_async16(uint32_t saddr, const void* gaddr) {
    asm volatile("cp.async.cg.shared.global [%0], [%1], 16;"
                 :: "r"(saddr), "l"(gaddr) : "memory");
}
__device__ __forceinline__ void cp_commit() {
    asm volatile("cp.async.commit_group;" ::: "memory");
}
template <int N> __device__ __forceinline__ void cp_wait() {
    asm volatile("cp.async.wait_group %0;" :: "n"(N) : "memory");
}
// pack two fp32 -> f16x2 (lo, hi), RN
__device__ __forceinline__ uint32_t pack_h2(float lo, float hi) {
    uint32_t r;
    asm("cvt.rn.f16x2.f32 %0, %1, %2;" : "=r"(r) : "f"(hi), "f"(lo));
    return r;
}
__device__ __forceinline__ void mma_f16(float* d, const uint32_t* a, const uint32_t* b) {
    asm volatile(
        "mma.sync.aligned.m16n8k16.row.col.f32.f16.f16.f32 "
        "{%0,%1,%2,%3}, {%4,%5,%6,%7}, {%8,%9}, {%0,%1,%2,%3};"
        : "+f"(d[0]), "+f"(d[1]), "+f"(d[2]), "+f"(d[3])
        : "r"(a[0]), "r"(a[1]), "r"(a[2]), "r"(a[3]), "r"(b[0]), "r"(b[1]));
}
__device__ __forceinline__ void ldmx4t(uint32_t& r0, uint32_t& r1,
                                       uint32_t& r2, uint32_t& r3, uint32_t addr) {
    asm volatile("ldmatrix.sync.aligned.m8n8.x4.trans.shared.b16 {%0,%1,%2,%3}, [%4];"
                 : "=r"(r0), "=r"(r1), "=r"(r2), "=r"(r3) : "r"(addr));
}

// Swizzled fp16 tile accessors.
// 128B rows (64 halves): chunk c (16B) of row r stored at c^(r&7).
__device__ __forceinline__ uint32_t lds32_r128(const char* base, int r, int ch) {
    return *(const uint32_t*)(base + r * 128 + ((((ch >> 3) ^ (r & 7)) << 4) | ((ch & 7) << 1)));
}
// 256B rows (128 halves): chunk c (0..15) stored at c^(r&7) (low 3 bits XOR).
__device__ __forceinline__ uint32_t lds32_r256(const char* base, int r, int ch) {
    return *(const uint32_t*)(base + r * 256 + ((((ch >> 3) ^ (r & 7)) << 4) | ((ch & 7) << 1)));
}

// ---------------------------------------------------------------------------
// fp32 -> fp16 conversion (RN)
// ---------------------------------------------------------------------------
__global__ void h_cvt_kernel(const float4* __restrict__ in,
                             uint2* __restrict__ out, int n4) {
    int i = blockIdx.x * blockDim.x + threadIdx.x;
    if (i < n4) {
        float4 v = in[i];
        out[i] = make_uint2(pack_h2(v.x, v.y), pack_h2(v.z, v.w));
    }
}

// ---------------------------------------------------------------------------
// fp16 HMMA GEMM: C[M,N] = A[M,K] * B[N,K]^T, fp32 accumulate.
// 128x128 CTA tile, BK=64 halves (128B rows), 3-stage cp.async pipeline,
// 8 warps (4m x 2n), warp tile 32x64 via m16n8k16.
// ---------------------------------------------------------------------------
#define BKH 64
#define GTILE_BYTES (128 * BKH * 2)        // 16384
#define GSTAGE_BYTES (2 * GTILE_BYTES)     // 32768
#define GEMM_SMEM_BYTES (3 * GSTAGE_BYTES) // 98304

__device__ __forceinline__ void load_stage_h(uint32_t sbase,
                                             const __half* __restrict__ A,
                                             const __half* __restrict__ B,
                                             int K, int arow0, int brow0, int k0,
                                             int tid) {
    #pragma unroll
    for (int i = 0; i < 4; ++i) {
        int idx = tid + i * 256;           // 0..1023
        int r = idx >> 3;                  // 0..127
        int c = idx & 7;                   // 16B chunk (8 halves)
        uint32_t soff = (uint32_t)(r * 128 + ((c ^ (r & 7)) << 4));
        cp_async16(sbase + soff, A + (size_t)(arow0 + r) * K + k0 + c * 8);
    }
    #pragma unroll
    for (int i = 0; i < 4; ++i) {
        int idx = tid + i * 256;
        int r = idx >> 3;
        int c = idx & 7;
        uint32_t soff = (uint32_t)(r * 128 + ((c ^ (r & 7)) << 4));
        cp_async16(sbase + GTILE_BYTES + soff, B + (size_t)(brow0 + r) * K + k0 + c * 8);
    }
    cp_commit();
}

template <bool HALF_OUT>
__global__ __launch_bounds__(256, 2)
void gemm_f16_kernel(const __half* __restrict__ A,
                     const __half* __restrict__ B,
                     void* __restrict__ Cv,
                     int M, int N, int K)
{
    extern __shared__ char smem[];
    const uint32_t sbase = smem_u32(smem);
    const int tid  = threadIdx.x;
    const int wid  = tid >> 5;
    const int lane = tid & 31;
    const int wm   = wid >> 1;
    const int wn   = wid & 1;
    const int g    = lane >> 2;
    const int t    = lane & 3;
    const int bm0 = blockIdx.y * 128;
    const int bn0 = blockIdx.x * 128;

    float acc[2][8][4];
    #pragma unroll
    for (int mt = 0; mt < 2; ++mt)
        #pragma unroll
        for (int nt = 0; nt < 8; ++nt)
            #pragma unroll
            for (int i = 0; i < 4; ++i) acc[mt][nt][i] = 0.0f;

    const int KT = K / BKH;   // 32

    load_stage_h(sbase + 0 * GSTAGE_BYTES, A, B, K, bm0, bn0, 0 * BKH, tid);
    load_stage_h(sbase + 1 * GSTAGE_BYTES, A, B, K, bm0, bn0, 1 * BKH, tid);

    for (int kt = 0; kt < KT; ++kt) {
        const int s = kt % 3;
        if (kt == KT - 1) cp_wait<0>(); else cp_wait<1>();
        __syncthreads();

        if (kt + 2 < KT)
            load_stage_h(sbase + (uint32_t)((kt + 2) % 3) * GSTAGE_BYTES, A, B, K,
                         bm0, bn0, (kt + 2) * BKH, tid);

        const char* Abase = smem + (size_t)s * GSTAGE_BYTES;
        const char* Bbase = Abase + GTILE_BYTES;

        #pragma unroll
        for (int ks = 0; ks < 4; ++ks) {
            const int k = ks * 16;
            uint32_t a[2][4];
            #pragma unroll
            for (int mt = 0; mt < 2; ++mt) {
                int r0 = wm * 32 + mt * 16 + g;
                a[mt][0] = lds32_r128(Abase, r0,     k + 2 * t);
                a[mt][1] = lds32_r128(Abase, r0 + 8, k + 2 * t);
                a[mt][2] = lds32_r128(Abase, r0,     k + 8 + 2 * t);
                a[mt][3] = lds32_r128(Abase, r0 + 8, k + 8 + 2 * t);
            }
            #pragma unroll
            for (int nt = 0; nt < 8; ++nt) {
                int rb = wn * 64 + nt * 8 + g;
                uint32_t b[2];
                b[0] = lds32_r128(Bbase, rb, k + 2 * t);
                b[1] = lds32_r128(Bbase, rb, k + 8 + 2 * t);
                mma_f16(acc[0][nt], a[0], b);
                mma_f16(acc[1][nt], a[1], b);
            }
        }
    }

    #pragma unroll
    for (int mt = 0; mt < 2; ++mt) {
        int row = bm0 + wm * 32 + mt * 16 + g;
        #pragma unroll
        for (int nt = 0; nt < 8; ++nt) {
            int col = bn0 + wn * 64 + nt * 8 + t * 2;
            if (HALF_OUT) {
                __half* C = (__half*)Cv;
                *(uint32_t*)(C + (size_t)row * N + col) =
                    pack_h2(acc[mt][nt][0], acc[mt][nt][1]);
                *(uint32_t*)(C + (size_t)(row + 8) * N + col) =
                    pack_h2(acc[mt][nt][2], acc[mt][nt][3]);
            } else {
                float* C = (float*)Cv;
                *(float2*)(C + (size_t)row * N + col) =
                    make_float2(acc[mt][nt][0], acc[mt][nt][1]);
                *(float2*)(C + (size_t)(row + 8) * N + col) =
                    make_float2(acc[mt][nt][2], acc[mt][nt][3]);
            }
        }
    }
}

// ---------------------------------------------------------------------------
// fp16 tensor-core causal flash attention (fp32 accumulate/softmax).
// Q-tile 128, KV-tile 64, 8 warps (16 q-rows each). Q/K/V fp16 swizzled smem,
// KV double-buffered. PV A-operand comes straight from score accumulators
// (no shuffles); V B-operand via ldmatrix.x4.trans.
// ---------------------------------------------------------------------------
#define QT  128
#define KVT 64
#define ATT_Q_BYTES  (QT * 256)                   // 32768
#define ATT_K_BYTES  (KVT * 256)                  // 16384
#define ATT_K_OFF    ATT_Q_BYTES
#define ATT_V_OFF    (ATT_K_OFF + 2 * ATT_K_BYTES)
#define ATT_SMEM_BYTES (ATT_V_OFF + 2 * ATT_K_BYTES)   // 98304

__device__ __forceinline__ void attn_load_kv(uint32_t sbase, int stage,
                                             const __half* __restrict__ KV,
                                             size_t gbase, int k0, int tid) {
    // K tile: 64 rows x 128 halves
    #pragma unroll
    for (int i = 0; i < 4; ++i) {
        int idx = tid + i * 256;           // 0..1023
        int r = idx >> 4;                  // 0..63
        int c = idx & 15;                  // 16B chunk
        uint32_t dst = sbase + ATT_K_OFF + (uint32_t)stage * ATT_K_BYTES
                     + (uint32_t)(r * 256 + ((c ^ (r & 7)) << 4));
        cp_async16(dst, KV + gbase + 2048 + (size_t)(k0 + r) * NQKV + c * 8);
    }
    // V tile
    #pragma unroll
    for (int i = 0; i < 4; ++i) {
        int idx = tid + i * 256;
        int r = idx >> 4;
        int c = idx & 15;
        uint32_t dst = sbase + ATT_V_OFF + (uint32_t)stage * ATT_K_BYTES
                     + (uint32_t)(r * 256 + ((c ^ (r & 7)) << 4));
        cp_async16(dst, KV + gbase + 4096 + (size_t)(k0 + r) * NQKV + c * 8);
    }
    cp_commit();
}

__global__ __launch_bounds__(256, 2)
void attn_f16_kernel(const __half* __restrict__ QKV,
                     __half* __restrict__ O)
{
    extern __shared__ char smc[];
    const uint32_t sbase = smem_u32(smc);

    const int tid  = threadIdx.x;
    const int wid  = tid >> 5;
    const int lane = tid & 31;
    const int g    = lane >> 2;
    const int t    = lane & 3;
    const int q0 = blockIdx.x * QT;
    const int h  = blockIdx.y;
    const int b  = blockIdx.z;
    const size_t gbase = ((size_t)b * S_LEN) * NQKV + (size_t)h * HD;
    const float scale = 0.08838834764831845f;  // 1/sqrt(128)

    // Q tile: 128 rows x 128 halves, swizzled.
    #pragma unroll
    for (int i = 0; i < 8; ++i) {
        int idx = tid + i * 256;           // 0..2047
        int r = idx >> 4;                  // 0..127
        int c = idx & 15;
        uint32_t dst = sbase + (uint32_t)(r * 256 + ((c ^ (r & 7)) << 4));
        cp_async16(dst, QKV + gbase + (size_t)(q0 + r) * NQKV + c * 8);
    }
    attn_load_kv(sbase, 0, QKV, gbase, 0, tid);

    float o[16][4];
    #pragma unroll
    for (int j = 0; j < 16; ++j)
        #pragma unroll
        for (int i = 0; i < 4; ++i) o[j][i] = 0.0f;
    float m2[2] = {-INFINITY, -INFINITY};
    float l2[2] = {0.0f, 0.0f};

    const int r0 = wid * 16;
    const int ntiles = q0 / KVT + 2;

    for (int tt = 0; tt < ntiles; ++tt) {
        const int s = tt & 1;
        cp_wait<0>();
        __syncthreads();
        if (tt + 1 < ntiles)
            attn_load_kv(sbase, s ^ 1, QKV, gbase, (tt + 1) * KVT, tid);

        const int kk0 = tt * KVT;
        if (kk0 <= q0 + r0 + 15) {
            const char* Qb = smc;
            const char* Kb = smc + ATT_K_OFF + s * ATT_K_BYTES;
            const uint32_t vb = sbase + ATT_V_OFF + (uint32_t)s * ATT_K_BYTES;

            // ---- QK^T: 16x64 scores per warp (8 k16-steps x 8 n8-tiles) ----
            float sc[8][4];
            #pragma unroll
            for (int j = 0; j < 8; ++j)
                #pragma unroll
                for (int i = 0; i < 4; ++i) sc[j][i] = 0.0f;

            #pragma unroll
            for (int ks = 0; ks < 8; ++ks) {
                const int k = ks * 16;
                uint32_t a[4];
                a[0] = lds32_r256(Qb, r0 + g,     k + 2 * t);
                a[1] = lds32_r256(Qb, r0 + g + 8, k + 2 * t);
                a[2] = lds32_r256(Qb, r0 + g,     k + 8 + 2 * t);
                a[3] = lds32_r256(Qb, r0 + g + 8, k + 8 + 2 * t);
                #pragma unroll
                for (int j = 0; j < 8; ++j) {
                    uint32_t bb[2];
                    bb[0] = lds32_r256(Kb, j * 8 + g, k + 2 * t);
                    bb[1] = lds32_r256(Kb, j * 8 + g, k + 8 + 2 * t);
                    mma_f16(sc[j], a, bb);
                }
            }

            // ---- causal mask (diagonal tiles only) ----
            if (kk0 + KVT - 1 > q0 + r0) {
                #pragma unroll
                for (int j = 0; j < 8; ++j) {
                    int colb = kk0 + j * 8 + 2 * t;
                    int rowa = q0 + r0 + g;
                    if (colb     > rowa)     sc[j][0] = -INFINITY;
                    if (colb + 1 > rowa)     sc[j][1] = -INFINITY;
                    if (colb     > rowa + 8) sc[j][2] = -INFINITY;
                    if (colb + 1 > rowa + 8) sc[j][3] = -INFINITY;
                }
            }

            // ---- online softmax (rows g and g+8) ----
            float alpha2[2];
            #pragma unroll
            for (int half = 0; half < 2; ++half) {
                const int i0 = half * 2;
                float rmax = -INFINITY;
                #pragma unroll
                for (int j = 0; j < 8; ++j)
                    rmax = fmaxf(rmax, fmaxf(sc[j][i0], sc[j][i0 + 1]));
                rmax = fmaxf(rmax, __shfl_xor_sync(0xffffffffu, rmax, 1));
                rmax = fmaxf(rmax, __shfl_xor_sync(0xffffffffu, rmax, 2));
                float mold = m2[half];
                float mnew = fmaxf(mold, rmax);
                float alpha = __expf((mold - mnew) * scale);
                float rsum = 0.0f;
                #pragma unroll
                for (int j = 0; j < 8; ++j) {
                    float p0 = __expf((sc[j][i0]     - mnew) * scale);
                    float p1 = __expf((sc[j][i0 + 1] - mnew) * scale);
                    sc[j][i0] = p0; sc[j][i0 + 1] = p1;
                    rsum += p0 + p1;
                }
                rsum += __shfl_xor_sync(0xffffffffu, rsum, 1);
                rsum += __shfl_xor_sync(0xffffffffu, rsum, 2);
                l2[half] = l2[half] * alpha + rsum;
                m2[half] = mnew;
                alpha2[half] = alpha;
            }
            #pragma unroll
            for (int j = 0; j < 16; ++j) {
                o[j][0] *= alpha2[0]; o[j][1] *= alpha2[0];
                o[j][2] *= alpha2[1]; o[j][3] *= alpha2[1];
            }

            // ---- PV: O += P @ V (P fragments direct from score accums) ----
            #pragma unroll
            for (int kk = 0; kk < 4; ++kk) {
                uint32_t a[4];
                a[0] = pack_h2(sc[2 * kk][0],     sc[2 * kk][1]);
                a[1] = pack_h2(sc[2 * kk][2],     sc[2 * kk][3]);
                a[2] = pack_h2(sc[2 * kk + 1][0], sc[2 * kk + 1][1]);
                a[3] = pack_h2(sc[2 * kk + 1][2], sc[2 * kk + 1][3]);
                #pragma unroll
                for (int pair = 0; pair < 8; ++pair) {
                    // ldmatrix.x4.trans: k16 x n16 block of V.
                    int vrow = kk * 16 + (lane & 15);
                    int ch = pair * 2 + (lane >> 4);   // 16B chunk (8 halves)
                    uint32_t addr = vb + (uint32_t)(vrow * 256 + ((ch ^ (vrow & 7)) << 4));
                    uint32_t v0, v1, v2, v3;
                    ldmx4t(v0, v1, v2, v3, addr);
                    uint32_t b0[2] = {v0, v1};
                    uint32_t b1[2] = {v2, v3};
                    mma_f16(o[pair * 2],     a, b0);
                    mma_f16(o[pair * 2 + 1], a, b1);
                }
            }
        }
    }

    // ---- epilogue: normalize, store fp16 O [MROWS x D_DIM] ----
    const float inv0 = 1.0f / l2[0];
    const float inv1 = 1.0f / l2[1];
    const int rowa = q0 + r0 + g;
    const size_t obase = ((size_t)b * S_LEN) * D_DIM + (size_t)h * HD;
    #pragma unroll
    for (int j = 0; j < 16; ++j) {
        int col = j * 8 + 2 * t;
        *(uint32_t*)(O + obase + (size_t)rowa * D_DIM + col) =
            pack_h2(o[j][0] * inv0, o[j][1] * inv0);
        *(uint32_t*)(O + obase + (size_t)(rowa + 8) * D_DIM + col) =
            pack_h2(o[j][2] * inv1, o[j][3] * inv1);
    }
}

// ---------------------------------------------------------------------------
// Launch
// ---------------------------------------------------------------------------
extern "C" void kernel_launch(void* const* d_in, const int* in_sizes, int n_in,
                              void* d_out, int out_size)
{
    const float* x  = (const float*)d_in[0];
    const float* wq = (const float*)d_in[1];
    const float* wk = (const float*)d_in[2];
    const float* wv = (const float*)d_in[3];
    const float* wo = (const float*)d_in[4];
    float* out = (float*)d_out;

    __half *xh, *wqkvh, *woh, *qkvh, *oh;
    cudaGetSymbolAddress((void**)&xh,    g_xh);
    cudaGetSymbolAddress((void**)&wqkvh, g_wqkvh);
    cudaGetSymbolAddress((void**)&woh,   g_woh);
    cudaGetSymbolAddress((void**)&qkvh,  g_QKVh);
    cudaGetSymbolAddress((void**)&oh,    g_Oh);

    static bool attr_set = false;
    if (!attr_set) {
        cudaFuncSetAttribute(attn_f16_kernel,
                             cudaFuncAttributeMaxDynamicSharedMemorySize,
                             ATT_SMEM_BYTES);
        cudaFuncSetAttribute(gemm_f16_kernel<true>,
                             cudaFuncAttributeMaxDynamicSharedMemorySize,
                             GEMM_SMEM_BYTES);
        cudaFuncSetAttribute(gemm_f16_kernel<false>,
                             cudaFuncAttributeMaxDynamicSharedMemorySize,
                             GEMM_SMEM_BYTES);
        attr_set = true;
    }

    const int n4x = MROWS * D_DIM / 4;       // 4194304
    const int n4w = D_DIM * D_DIM / 4;       // 1048576
    const size_t wstep = (size_t)D_DIM * D_DIM;

    // fp32 -> fp16 (RN)
    h_cvt_kernel<<<n4x / 256, 256>>>((const float4*)x,  (uint2*)xh, n4x);
    h_cvt_kernel<<<n4w / 256, 256>>>((const float4*)wq, (uint2*)(wqkvh),             n4w);
    h_cvt_kernel<<<n4w / 256, 256>>>((const float4*)wk, (uint2*)(wqkvh + wstep),     n4w);
    h_cvt_kernel<<<n4w / 256, 256>>>((const float4*)wv, (uint2*)(wqkvh + 2 * wstep), n4w);
    h_cvt_kernel<<<n4w / 256, 256>>>((const float4*)wo, (uint2*)woh, n4w);

    // Fused QKV projection: one GEMM, N = 6144, fp16 output.
    dim3 qkv_grid(NQKV / 128, MROWS / 128);   // (48, 64)
    gemm_f16_kernel<true><<<qkv_grid, 256, GEMM_SMEM_BYTES>>>(
        xh, wqkvh, qkvh, MROWS, NQKV, D_DIM);

    // fp16 tensor-core causal flash attention.
    dim3 attn_grid(S_LEN / QT, NHEAD, B_SZ);  // (16, 16, 4)
    attn_f16_kernel<<<attn_grid, 256, ATT_SMEM_BYTES>>>(qkvh, oh);

    // Output projection: fp32 output.
    dim3 out_grid(D_DIM / 128, MROWS / 128);  // (16, 64)
    gemm_f16_kernel<false><<<out_grid, 256, GEMM_SMEM_BYTES>>>(
        oh, woh, out, MROWS, D_DIM, D_DIM);
}

// round 6
// speedup vs baseline: 8.0943x; 1.0686x over previous
#include <cuda_runtime.h>
#include <cuda_fp16.h>
#include <math.h>
#include <cstdint>

// Problem constants
#define D_DIM 2048
#define S_LEN 2048
#define B_SZ  4
#define NHEAD 16
#define HD    128
#define MROWS (B_SZ * S_LEN)   // 8192
#define NQKV  (3 * D_DIM)      // 6144

// ---------------------------------------------------------------------------
// Scratch (device globals: allocation-guard-safe)
// ---------------------------------------------------------------------------
__device__ __half g_xh[(size_t)MROWS * D_DIM];
__device__ __half g_wqkvh[(size_t)NQKV * D_DIM];     // [wq; wk; wv] rows
__device__ __half g_woh[(size_t)D_DIM * D_DIM];
__device__ __half g_QKVh[(size_t)MROWS * NQKV];      // Q|K|V per row
__device__ __half g_Oh[(size_t)MROWS * D_DIM];

// ---------------------------------------------------------------------------
// Helpers
// ---------------------------------------------------------------------------
__device__ __forceinline__ uint32_t smem_u32(const void* p) {
    uint32_t a;
    asm("{ .reg .u64 t; cvta.to.shared.u64 t, %1; cvt.u32.u64 %0, t; }"
        : "=r"(a) : "l"(p));
    return a;
}
__device__ __forceinline__ void cp_async16(uint32_t saddr, const void* gaddr) {
    asm volatile("cp.async.cg.shared.global [%0], [%1], 16;"
                 :: "r"(saddr), "l"(gaddr) : "memory");
}
__device__ __forceinline__ void cp_commit() {
    asm volatile("cp.async.commit_group;" ::: "memory");
}
template <int N> __device__ __forceinline__ void cp_wait() {
    asm volatile("cp.async.wait_group %0;" :: "n"(N) : "memory");
}
__device__ __forceinline__ uint32_t pack_h2(float lo, float hi) {
    uint32_t r;
    asm("cvt.rn.f16x2.f32 %0, %1, %2;" : "=r"(r) : "f"(hi), "f"(lo));
    return r;
}
__device__ __forceinline__ void mma_f16(float* d, const uint32_t* a, const uint32_t* b) {
    asm volatile(
        "mma.sync.aligned.m16n8k16.row.col.f32.f16.f16.f32 "
        "{%0,%1,%2,%3}, {%4,%5,%6,%7}, {%8,%9}, {%0,%1,%2,%3};"
        : "+f"(d[0]), "+f"(d[1]), "+f"(d[2]), "+f"(d[3])
        : "r"(a[0]), "r"(a[1]), "r"(a[2]), "r"(a[3]), "r"(b[0]), "r"(b[1]));
}
__device__ __forceinline__ void ldmx4(uint32_t& r0, uint32_t& r1,
                                      uint32_t& r2, uint32_t& r3, uint32_t addr) {
    asm volatile("ldmatrix.sync.aligned.m8n8.x4.shared.b16 {%0,%1,%2,%3}, [%4];"
                 : "=r"(r0), "=r"(r1), "=r"(r2), "=r"(r3) : "r"(addr));
}
__device__ __forceinline__ void ldmx4t(uint32_t& r0, uint32_t& r1,
                                       uint32_t& r2, uint32_t& r3, uint32_t addr) {
    asm volatile("ldmatrix.sync.aligned.m8n8.x4.trans.shared.b16 {%0,%1,%2,%3}, [%4];"
                 : "=r"(r0), "=r"(r1), "=r"(r2), "=r"(r3) : "r"(addr));
}

// ---------------------------------------------------------------------------
// fp32 -> fp16 conversion (RN)
// ---------------------------------------------------------------------------
__global__ void h_cvt_kernel(const float4* __restrict__ in,
                             uint2* __restrict__ out, int n4) {
    int i = blockIdx.x * blockDim.x + threadIdx.x;
    if (i < n4) {
        float4 v = in[i];
        out[i] = make_uint2(pack_h2(v.x, v.y), pack_h2(v.z, v.w));
    }
}
// 3 sources -> contiguous destination regions (for wq/wk/wv)
__global__ void h_cvt3_kernel(const float4* __restrict__ s0,
                              const float4* __restrict__ s1,
                              const float4* __restrict__ s2,
                              uint2* __restrict__ out, int n4each) {
    const float4* src = (blockIdx.y == 0) ? s0 : (blockIdx.y == 1) ? s1 : s2;
    int i = blockIdx.x * blockDim.x + threadIdx.x;
    if (i < n4each) {
        float4 v = src[i];
        out[(size_t)blockIdx.y * n4each + i] =
            make_uint2(pack_h2(v.x, v.y), pack_h2(v.z, v.w));
    }
}

// ---------------------------------------------------------------------------
// fp16 HMMA GEMM: C[M,N] = A[M,K] * B[N,K]^T, fp32 accumulate.
// 128x128 CTA tile, BK=64 halves (128B swizzled rows), 3-stage cp.async,
// 8 warps (4m x 2n), warp tile 32x64, ldmatrix.x4 fragment loads.
// ---------------------------------------------------------------------------
#define BKH 64
#define GTILE_BYTES (128 * BKH * 2)        // 16384
#define GSTAGE_BYTES (2 * GTILE_BYTES)     // 32768
#define GEMM_SMEM_BYTES (3 * GSTAGE_BYTES) // 98304

__device__ __forceinline__ void load_stage_h(uint32_t sbase,
                                             const __half* __restrict__ A,
                                             const __half* __restrict__ B,
                                             int K, int arow0, int brow0, int k0,
                                             int tid) {
    #pragma unroll
    for (int i = 0; i < 4; ++i) {
        int idx = tid + i * 256;
        int r = idx >> 3;
        int c = idx & 7;
        uint32_t soff = (uint32_t)(r * 128 + ((c ^ (r & 7)) << 4));
        cp_async16(sbase + soff, A + (size_t)(arow0 + r) * K + k0 + c * 8);
    }
    #pragma unroll
    for (int i = 0; i < 4; ++i) {
        int idx = tid + i * 256;
        int r = idx >> 3;
        int c = idx & 7;
        uint32_t soff = (uint32_t)(r * 128 + ((c ^ (r & 7)) << 4));
        cp_async16(sbase + GTILE_BYTES + soff, B + (size_t)(brow0 + r) * K + k0 + c * 8);
    }
    cp_commit();
}

template <bool HALF_OUT>
__global__ __launch_bounds__(256, 2)
void gemm_f16_kernel(const __half* __restrict__ A,
                     const __half* __restrict__ B,
                     void* __restrict__ Cv,
                     int M, int N, int K)
{
    extern __shared__ char smem[];
    const uint32_t sbase = smem_u32(smem);
    const int tid  = threadIdx.x;
    const int wid  = tid >> 5;
    const int lane = tid & 31;
    const int wm   = wid >> 1;
    const int wn   = wid & 1;
    const int g    = lane >> 2;
    const int t    = lane & 3;
    const int bm0 = blockIdx.y * 128;
    const int bn0 = blockIdx.x * 128;

    // ldmatrix lane roles
    const int lrow = lane & 15;           // row within 16-row block
    const int lch  = lane >> 4;           // +0 / +1 16B chunk

    float acc[2][8][4];
    #pragma unroll
    for (int mt = 0; mt < 2; ++mt)
        #pragma unroll
        for (int nt = 0; nt < 8; ++nt)
            #pragma unroll
            for (int i = 0; i < 4; ++i) acc[mt][nt][i] = 0.0f;

    const int KT = K / BKH;   // 32

    load_stage_h(sbase + 0 * GSTAGE_BYTES, A, B, K, bm0, bn0, 0 * BKH, tid);
    load_stage_h(sbase + 1 * GSTAGE_BYTES, A, B, K, bm0, bn0, 1 * BKH, tid);

    for (int kt = 0; kt < KT; ++kt) {
        const int s = kt % 3;
        if (kt == KT - 1) cp_wait<0>(); else cp_wait<1>();
        __syncthreads();

        if (kt + 2 < KT)
            load_stage_h(sbase + (uint32_t)((kt + 2) % 3) * GSTAGE_BYTES, A, B, K,
                         bm0, bn0, (kt + 2) * BKH, tid);

        const uint32_t abase = sbase + (uint32_t)s * GSTAGE_BYTES;
        const uint32_t bbase = abase + GTILE_BYTES;

        #pragma unroll
        for (int ks = 0; ks < 4; ++ks) {
            const int ch = ks * 2 + lch;
            uint32_t a0[4], a1[4];
            {
                int r = wm * 32 + lrow;
                ldmx4(a0[0], a0[1], a0[2], a0[3],
                      abase + (uint32_t)(r * 128 + ((ch ^ (r & 7)) << 4)));
                r += 16;
                ldmx4(a1[0], a1[1], a1[2], a1[3],
                      abase + (uint32_t)(r * 128 + ((ch ^ (r & 7)) << 4)));
            }
            #pragma unroll
            for (int nb = 0; nb < 4; ++nb) {
                int r = wn * 64 + nb * 16 + lrow;
                uint32_t bf[4];
                ldmx4(bf[0], bf[1], bf[2], bf[3],
                      bbase + (uint32_t)(r * 128 + ((ch ^ (r & 7)) << 4)));
                uint32_t be[2] = {bf[0], bf[2]};
                uint32_t bo[2] = {bf[1], bf[3]};
                mma_f16(acc[0][2 * nb],     a0, be);
                mma_f16(acc[0][2 * nb + 1], a0, bo);
                mma_f16(acc[1][2 * nb],     a1, be);
                mma_f16(acc[1][2 * nb + 1], a1, bo);
            }
        }
    }

    #pragma unroll
    for (int mt = 0; mt < 2; ++mt) {
        int row = bm0 + wm * 32 + mt * 16 + g;
        #pragma unroll
        for (int nt = 0; nt < 8; ++nt) {
            int col = bn0 + wn * 64 + nt * 8 + t * 2;
            if (HALF_OUT) {
                __half* C = (__half*)Cv;
                *(uint32_t*)(C + (size_t)row * N + col) =
                    pack_h2(acc[mt][nt][0], acc[mt][nt][1]);
                *(uint32_t*)(C + (size_t)(row + 8) * N + col) =
                    pack_h2(acc[mt][nt][2], acc[mt][nt][3]);
            } else {
                float* C = (float*)Cv;
                *(float2*)(C + (size_t)row * N + col) =
                    make_float2(acc[mt][nt][0], acc[mt][nt][1]);
                *(float2*)(C + (size_t)(row + 8) * N + col) =
                    make_float2(acc[mt][nt][2], acc[mt][nt][3]);
            }
        }
    }
}

// ---------------------------------------------------------------------------
// fp16 tensor-core causal flash attention (fp32 accumulate/softmax).
// Q-tile 128, KV-tile 64, 8 warps (16 q-rows each). ldmatrix fragment loads.
// ---------------------------------------------------------------------------
#define QT  128
#define KVT 64
#define ATT_Q_BYTES  (QT * 256)                   // 32768
#define ATT_K_BYTES  (KVT * 256)                  // 16384
#define ATT_K_OFF    ATT_Q_BYTES
#define ATT_V_OFF    (ATT_K_OFF + 2 * ATT_K_BYTES)
#define ATT_SMEM_BYTES (ATT_V_OFF + 2 * ATT_K_BYTES)   // 98304

__device__ __forceinline__ void attn_load_kv(uint32_t sbase, int stage,
                                             const __half* __restrict__ KV,
                                             size_t gbase, int k0, int tid) {
    #pragma unroll
    for (int i = 0; i < 4; ++i) {
        int idx = tid + i * 256;
        int r = idx >> 4;
        int c = idx & 15;
        uint32_t dst = sbase + ATT_K_OFF + (uint32_t)stage * ATT_K_BYTES
                     + (uint32_t)(r * 256 + ((c ^ (r & 7)) << 4));
        cp_async16(dst, KV + gbase + 2048 + (size_t)(k0 + r) * NQKV + c * 8);
    }
    #pragma unroll
    for (int i = 0; i < 4; ++i) {
        int idx = tid + i * 256;
        int r = idx >> 4;
        int c = idx & 15;
        uint32_t dst = sbase + ATT_V_OFF + (uint32_t)stage * ATT_K_BYTES
                     + (uint32_t)(r * 256 + ((c ^ (r & 7)) << 4));
        cp_async16(dst, KV + gbase + 4096 + (size_t)(k0 + r) * NQKV + c * 8);
    }
    cp_commit();
}

__global__ __launch_bounds__(256, 2)
void attn_f16_kernel(const __half* __restrict__ QKV,
                     __half* __restrict__ O)
{
    extern __shared__ char smc[];
    const uint32_t sbase = smem_u32(smc);

    const int tid  = threadIdx.x;
    const int wid  = tid >> 5;
    const int lane = tid & 31;
    const int g    = lane >> 2;
    const int t    = lane & 3;
    // Reverse q-block order: heaviest CTAs first (causal work ~ q0).
    const int q0 = (gridDim.x - 1 - blockIdx.x) * QT;
    const int h  = blockIdx.y;
    const int b  = blockIdx.z;
    const size_t gbase = ((size_t)b * S_LEN) * NQKV + (size_t)h * HD;
    const float scale = 0.08838834764831845f;  // 1/sqrt(128)

    const int lrow = lane & 15;
    const int lch  = lane >> 4;

    // Q tile: 128 rows x 128 halves, swizzled.
    #pragma unroll
    for (int i = 0; i < 8; ++i) {
        int idx = tid + i * 256;
        int r = idx >> 4;
        int c = idx & 15;
        uint32_t dst = sbase + (uint32_t)(r * 256 + ((c ^ (r & 7)) << 4));
        cp_async16(dst, QKV + gbase + (size_t)(q0 + r) * NQKV + c * 8);
    }
    attn_load_kv(sbase, 0, QKV, gbase, 0, tid);

    float o[16][4];
    #pragma unroll
    for (int j = 0; j < 16; ++j)
        #pragma unroll
        for (int i = 0; i < 4; ++i) o[j][i] = 0.0f;
    float m2[2] = {-INFINITY, -INFINITY};
    float l2[2] = {0.0f, 0.0f};

    const int r0 = wid * 16;
    const int ntiles = q0 / KVT + 2;

    for (int tt = 0; tt < ntiles; ++tt) {
        const int s = tt & 1;
        cp_wait<0>();
        __syncthreads();
        if (tt + 1 < ntiles)
            attn_load_kv(sbase, s ^ 1, QKV, gbase, (tt + 1) * KVT, tid);

        const int kk0 = tt * KVT;
        if (kk0 <= q0 + r0 + 15) {
            const uint32_t kb = sbase + ATT_K_OFF + (uint32_t)s * ATT_K_BYTES;
            const uint32_t vb = sbase + ATT_V_OFF + (uint32_t)s * ATT_K_BYTES;

            // ---- QK^T: 16x64 scores per warp; ldmatrix frags ----
            float sc[8][4];
            #pragma unroll
            for (int j = 0; j < 8; ++j)
                #pragma unroll
                for (int i = 0; i < 4; ++i) sc[j][i] = 0.0f;

            #pragma unroll
            for (int ks = 0; ks < 8; ++ks) {
                const int ch = ks * 2 + lch;
                uint32_t a[4];
                {
                    int r = r0 + lrow;
                    ldmx4(a[0], a[1], a[2], a[3],
                          sbase + (uint32_t)(r * 256 + ((ch ^ (r & 7)) << 4)));
                }
                #pragma unroll
                for (int nb = 0; nb < 4; ++nb) {
                    int r = nb * 16 + lrow;
                    uint32_t bf[4];
                    ldmx4(bf[0], bf[1], bf[2], bf[3],
                          kb + (uint32_t)(r * 256 + ((ch ^ (r & 7)) << 4)));
                    uint32_t be[2] = {bf[0], bf[2]};
                    uint32_t bo[2] = {bf[1], bf[3]};
                    mma_f16(sc[2 * nb],     a, be);
                    mma_f16(sc[2 * nb + 1], a, bo);
                }
            }

            // ---- causal mask (diagonal tiles only) ----
            if (kk0 + KVT - 1 > q0 + r0) {
                #pragma unroll
                for (int j = 0; j < 8; ++j) {
                    int colb = kk0 + j * 8 + 2 * t;
                    int rowa = q0 + r0 + g;
                    if (colb     > rowa)     sc[j][0] = -INFINITY;
                    if (colb + 1 > rowa)     sc[j][1] = -INFINITY;
                    if (colb     > rowa + 8) sc[j][2] = -INFINITY;
                    if (colb + 1 > rowa + 8) sc[j][3] = -INFINITY;
                }
            }

            // ---- online softmax (rows g and g+8) ----
            float alpha2[2];
            #pragma unroll
            for (int half = 0; half < 2; ++half) {
                const int i0 = half * 2;
                float rmax = -INFINITY;
                #pragma unroll
                for (int j = 0; j < 8; ++j)
                    rmax = fmaxf(rmax, fmaxf(sc[j][i0], sc[j][i0 + 1]));
                rmax = fmaxf(rmax, __shfl_xor_sync(0xffffffffu, rmax, 1));
                rmax = fmaxf(rmax, __shfl_xor_sync(0xffffffffu, rmax, 2));
                float mold = m2[half];
                float mnew = fmaxf(mold, rmax);
                float alpha = __expf((mold - mnew) * scale);
                float rsum = 0.0f;
                #pragma unroll
                for (int j = 0; j < 8; ++j) {
                    float p0 = __expf((sc[j][i0]     - mnew) * scale);
                    float p1 = __expf((sc[j][i0 + 1] - mnew) * scale);
                    sc[j][i0] = p0; sc[j][i0 + 1] = p1;
                    rsum += p0 + p1;
                }
                rsum += __shfl_xor_sync(0xffffffffu, rsum, 1);
                rsum += __shfl_xor_sync(0xffffffffu, rsum, 2);
                l2[half] = l2[half] * alpha + rsum;
                m2[half] = mnew;
                alpha2[half] = alpha;
            }
            #pragma unroll
            for (int j = 0; j < 16; ++j) {
                o[j][0] *= alpha2[0]; o[j][1] *= alpha2[0];
                o[j][2] *= alpha2[1]; o[j][3] *= alpha2[1];
            }

            // ---- PV: O += P @ V (P frags direct from score accums) ----
            #pragma unroll
            for (int kk = 0; kk < 4; ++kk) {
                uint32_t a[4];
                a[0] = pack_h2(sc[2 * kk][0],     sc[2 * kk][1]);
                a[1] = pack_h2(sc[2 * kk][2],     sc[2 * kk][3]);
                a[2] = pack_h2(sc[2 * kk + 1][0], sc[2 * kk + 1][1]);
                a[3] = pack_h2(sc[2 * kk + 1][2], sc[2 * kk + 1][3]);
                #pragma unroll
                for (int pair = 0; pair < 8; ++pair) {
                    int vrow = kk * 16 + (lane & 15);
                    int ch = pair * 2 + (lane >> 4);
                    uint32_t addr = vb + (uint32_t)(vrow * 256 + ((ch ^ (vrow & 7)) << 4));
                    uint32_t v0, v1, v2, v3;
                    ldmx4t(v0, v1, v2, v3, addr);
                    uint32_t b0[2] = {v0, v1};
                    uint32_t b1[2] = {v2, v3};
                    mma_f16(o[pair * 2],     a, b0);
                    mma_f16(o[pair * 2 + 1], a, b1);
                }
            }
        }
    }

    // ---- epilogue: normalize, store fp16 O [MROWS x D_DIM] ----
    const float inv0 = 1.0f / l2[0];
    const float inv1 = 1.0f / l2[1];
    const int rowa = q0 + r0 + g;
    const size_t obase = ((size_t)b * S_LEN) * D_DIM + (size_t)h * HD;
    #pragma unroll
    for (int j = 0; j < 16; ++j) {
        int col = j * 8 + 2 * t;
        *(uint32_t*)(O + obase + (size_t)rowa * D_DIM + col) =
            pack_h2(o[j][0] * inv0, o[j][1] * inv0);
        *(uint32_t*)(O + obase + (size_t)(rowa + 8) * D_DIM + col) =
            pack_h2(o[j][2] * inv1, o[j][3] * inv1);
    }
}

// ---------------------------------------------------------------------------
// Launch
// ---------------------------------------------------------------------------
extern "C" void kernel_launch(void* const* d_in, const int* in_sizes, int n_in,
                              void* d_out, int out_size)
{
    const float* x  = (const float*)d_in[0];
    const float* wq = (const float*)d_in[1];
    const float* wk = (const float*)d_in[2];
    const float* wv = (const float*)d_in[3];
    const float* wo = (const float*)d_in[4];
    float* out = (float*)d_out;

    __half *xh, *wqkvh, *woh, *qkvh, *oh;
    cudaGetSymbolAddress((void**)&xh,    g_xh);
    cudaGetSymbolAddress((void**)&wqkvh, g_wqkvh);
    cudaGetSymbolAddress((void**)&woh,   g_woh);
    cudaGetSymbolAddress((void**)&qkvh,  g_QKVh);
    cudaGetSymbolAddress((void**)&oh,    g_Oh);

    static bool attr_set = false;
    if (!attr_set) {
        cudaFuncSetAttribute(attn_f16_kernel,
                             cudaFuncAttributeMaxDynamicSharedMemorySize,
                             ATT_SMEM_BYTES);
        cudaFuncSetAttribute(gemm_f16_kernel<true>,
                             cudaFuncAttributeMaxDynamicSharedMemorySize,
                             GEMM_SMEM_BYTES);
        cudaFuncSetAttribute(gemm_f16_kernel<false>,
                             cudaFuncAttributeMaxDynamicSharedMemorySize,
                             GEMM_SMEM_BYTES);
        attr_set = true;
    }

    const int n4x = MROWS * D_DIM / 4;       // 4194304
    const int n4w = D_DIM * D_DIM / 4;       // 1048576

    // fp32 -> fp16 (RN)
    h_cvt_kernel<<<n4x / 256, 256>>>((const float4*)x, (uint2*)xh, n4x);
    dim3 cvt3_grid(n4w / 256, 3);
    h_cvt3_kernel<<<cvt3_grid, 256>>>((const float4*)wq, (const float4*)wk,
                                      (const float4*)wv, (uint2*)wqkvh, n4w);
    h_cvt_kernel<<<n4w / 256, 256>>>((const float4*)wo, (uint2*)woh, n4w);

    // Fused QKV projection: one GEMM, N = 6144, fp16 output.
    dim3 qkv_grid(NQKV / 128, MROWS / 128);   // (48, 64)
    gemm_f16_kernel<true><<<qkv_grid, 256, GEMM_SMEM_BYTES>>>(
        xh, wqkvh, qkvh, MROWS, NQKV, D_DIM);

    // fp16 tensor-core causal flash attention.
    dim3 attn_grid(S_LEN / QT, NHEAD, B_SZ);  // (16, 16, 4)
    attn_f16_kernel<<<attn_grid, 256, ATT_SMEM_BYTES>>>(qkvh, oh);

    // Output projection: fp32 output.
    dim3 out_grid(D_DIM / 128, MROWS / 128);  // (16, 64)
    gemm_f16_kernel<false><<<out_grid, 256, GEMM_SMEM_BYTES>>>(
        oh, woh, out, MROWS, D_DIM, D_DIM);
}